// round 2
// baseline (speedup 1.0000x reference)
#include <cuda_runtime.h>
#include <cstdint>

#define NPTS  40960
#define BATCH 4
#define KNN   16
#define DCH   64
#define HCH   32

// scratch: f = relu(bn(W2 @ feature))  -> [B*N][H]
__device__ float f_buf[(size_t)BATCH * NPTS * HCH];
__device__ int   g_is64;

// ---------------------------------------------------------------------------
// Detect whether neigh_idx buffer holds int64 or int32 values.
// For int64 data, every value read as int64 lies in [0, NPTS). For int32 data,
// an int64-read combines two random int32 indices -> almost never in range.
// ---------------------------------------------------------------------------
__global__ void detect_idx_kind(const void* __restrict__ idx) {
    const long long* p = (const long long*)idx;
    int lane = threadIdx.x & 31;
    int cnt = 0;
    for (int i = lane; i < 256; i += 32) {
        long long v = p[i];
        if (v >= 0 && v < NPTS) cnt++;
    }
    #pragma unroll
    for (int o = 16; o; o >>= 1) cnt += __shfl_down_sync(0xffffffffu, cnt, o);
    if (lane == 0) g_is64 = (cnt > 128) ? 1 : 0;
}

// ---------------------------------------------------------------------------
// conv2: f[b,n,h] = relu( (sum_d W2[h,d] * feature[b,d,n]) * g2[h]/sqrt(1+eps) + b2[h] )
// warp per point, lane = h.
// ---------------------------------------------------------------------------
__global__ void __launch_bounds__(256) conv2_kernel(
    const float* __restrict__ feature,
    const float* __restrict__ W2,
    const float* __restrict__ g2,
    const float* __restrict__ b2)
{
    __shared__ float W2t[DCH * HCH];   // [d][h]
    int tid = threadIdx.x;
    for (int i = tid; i < DCH * HCH; i += 256) {
        int d = i >> 5, h = i & 31;
        W2t[i] = W2[h * DCH + d];
    }
    __syncthreads();

    int warp = tid >> 5, lane = tid & 31;
    int p = blockIdx.x * 8 + warp;
    int b = p / NPTS, n = p % NPTS;

    const float* fp = feature + (size_t)b * DCH * NPTS + n;
    float acc = 0.f;
    #pragma unroll
    for (int d = 0; d < DCH; d++)
        acc = fmaf(W2t[d * HCH + lane], __ldg(fp + (size_t)d * NPTS), acc);

    const float RS = rsqrtf(1.00001f);
    float f = fmaxf(fmaf(acc, __ldg(g2 + lane) * RS, __ldg(b2 + lane)), 0.f);
    f_buf[((size_t)b * NPTS + n) * HCH + lane] = f;
}

// ---------------------------------------------------------------------------
// Fused conv1 + gather + conv3 + maxpool + conv4.
// warp per point, lane = h. W1/W3 rows live in registers; per-k concat vector
// staged in 256B of per-warp smem and consumed via broadcast float4 LDS.
// ---------------------------------------------------------------------------
__global__ void __launch_bounds__(256) main_kernel(
    const float* __restrict__ xyz,
    const void*  __restrict__ nidx,
    const float* __restrict__ W1, const float* __restrict__ g1, const float* __restrict__ b1,
    const float* __restrict__ W3, const float* __restrict__ g3, const float* __restrict__ b3,
    const float* __restrict__ W4, const float* __restrict__ g4, const float* __restrict__ b4,
    float* __restrict__ out)
{
    __shared__ float  W4t[DCH * DCH];   // [c][d]  (transposed W4)
    __shared__ float4 bufv[8][16];      // per-warp 64-float staging

    int tid = threadIdx.x;
    for (int i = tid; i < DCH * DCH; i += 256) {
        int c = i >> 6, d = i & 63;
        W4t[i] = W4[d * DCH + c];
    }
    __syncthreads();

    int warp = tid >> 5, lane = tid & 31;
    int p = blockIdx.x * 8 + warp;
    int b = p / NPTS, n = p % NPTS;

    const float RS  = rsqrtf(1.00001f);
    float s1 = __ldg(g1 + lane) * RS, b1v = __ldg(b1 + lane);
    float s3 = __ldg(g3 + lane) * RS, b3v = __ldg(b3 + lane);

    float W1r[10];
    #pragma unroll
    for (int i = 0; i < 10; i++) W1r[i] = __ldg(W1 + lane * 10 + i);

    float W3r[64];
    {
        const float4* W3v = (const float4*)(W3 + lane * 64);
        #pragma unroll
        for (int i = 0; i < 16; i++) {
            float4 v = __ldg(W3v + i);
            W3r[4 * i + 0] = v.x; W3r[4 * i + 1] = v.y;
            W3r[4 * i + 2] = v.z; W3r[4 * i + 3] = v.w;
        }
    }

    int is64 = g_is64;
    int jj = 0;
    {
        size_t off = ((size_t)(b * NPTS + n)) * KNN;
        if (lane < KNN)
            jj = is64 ? (int)((const long long*)nidx)[off + lane]
                      : ((const int*)nidx)[off + lane];
    }

    const float* xb = xyz + (size_t)b * NPTS * 3;
    float cx = __ldg(xb + n * 3 + 0);
    float cy = __ldg(xb + n * 3 + 1);
    float cz = __ldg(xb + n * 3 + 2);

    float* buf = (float*)&bufv[warp][0];
    const float* fbb = f_buf + (size_t)b * NPTS * HCH;

    // prefetch k = 0
    int j0 = __shfl_sync(0xffffffffu, jj, 0);
    float px = __ldg(xb + j0 * 3 + 0);
    float py = __ldg(xb + j0 * 3 + 1);
    float pz = __ldg(xb + j0 * 3 + 2);
    float fn = fbb[(size_t)j0 * HCH + lane];

    float m = -1e30f;
    #pragma unroll 1
    for (int k = 0; k < KNN; k++) {
        float cpx = px, cpy = py, cpz = pz, cfn = fn;
        if (k + 1 < KNN) {
            int j2 = __shfl_sync(0xffffffffu, jj, k + 1);
            px = __ldg(xb + j2 * 3 + 0);
            py = __ldg(xb + j2 * 3 + 1);
            pz = __ldg(xb + j2 * 3 + 2);
            fn = fbb[(size_t)j2 * HCH + lane];
        }
        float rx = cx - cpx, ry = cy - cpy, rz = cz - cpz;
        float dist = sqrtf(rx * rx + ry * ry + rz * rz);
        float dot = W1r[0] * dist;
        dot = fmaf(W1r[1], rx,  dot);
        dot = fmaf(W1r[2], ry,  dot);
        dot = fmaf(W1r[3], rz,  dot);
        dot = fmaf(W1r[4], cx,  dot);
        dot = fmaf(W1r[5], cy,  dot);
        dot = fmaf(W1r[6], cz,  dot);
        dot = fmaf(W1r[7], cpx, dot);
        dot = fmaf(W1r[8], cpy, dot);
        dot = fmaf(W1r[9], cpz, dot);
        float fx = fmaxf(fmaf(dot, s1, b1v), 0.f);

        buf[lane]      = cfn;
        buf[32 + lane] = fx;
        __syncwarp();

        float a = 0.f;
        #pragma unroll
        for (int c4 = 0; c4 < 16; c4++) {
            float4 v = bufv[warp][c4];
            a = fmaf(W3r[4 * c4 + 0], v.x, a);
            a = fmaf(W3r[4 * c4 + 1], v.y, a);
            a = fmaf(W3r[4 * c4 + 2], v.z, a);
            a = fmaf(W3r[4 * c4 + 3], v.w, a);
        }
        __syncwarp();

        float a3 = fmaxf(fmaf(a, s3, b3v), 0.f);
        m = fmaxf(m, a3);
    }

    // conv4 on [maxpooled (32) , f_center (32)]
    float fc = fbb[(size_t)n * HCH + lane];
    buf[lane]      = m;
    buf[32 + lane] = fc;
    __syncwarp();

    float s4a = __ldg(g4 + lane)      * RS, b4a = __ldg(b4 + lane);
    float s4b = __ldg(g4 + lane + 32) * RS, b4b = __ldg(b4 + lane + 32);

    float o0 = 0.f, o1 = 0.f;
    #pragma unroll
    for (int c4 = 0; c4 < 16; c4++) {
        float4 v = bufv[warp][c4];
        int c = 4 * c4;
        o0 = fmaf(W4t[(c + 0) * DCH + lane], v.x, o0);
        o0 = fmaf(W4t[(c + 1) * DCH + lane], v.y, o0);
        o0 = fmaf(W4t[(c + 2) * DCH + lane], v.z, o0);
        o0 = fmaf(W4t[(c + 3) * DCH + lane], v.w, o0);
        o1 = fmaf(W4t[(c + 0) * DCH + lane + 32], v.x, o1);
        o1 = fmaf(W4t[(c + 1) * DCH + lane + 32], v.y, o1);
        o1 = fmaf(W4t[(c + 2) * DCH + lane + 32], v.z, o1);
        o1 = fmaf(W4t[(c + 3) * DCH + lane + 32], v.w, o1);
    }
    o0 = fmaxf(fmaf(o0, s4a, b4a), 0.f);
    o1 = fmaxf(fmaf(o1, s4b, b4b), 0.f);

    out[((size_t)b * DCH + lane)      * NPTS + n] = o0;
    out[((size_t)b * DCH + lane + 32) * NPTS + n] = o1;
}

// ---------------------------------------------------------------------------
extern "C" void kernel_launch(void* const* d_in, const int* in_sizes, int n_in,
                              void* d_out, int out_size)
{
    const float *feature, *xyz, *W1, *W2, *W3, *W4;
    const float *g1, *b1, *g2, *b2, *g3, *b3, *g4, *b4;
    const void* nidx;

    if (in_sizes[2] == BATCH * NPTS * KNN) {
        // setup_inputs dict order:
        // feature, xyz, neigh_idx, W1, W2, W3, W4, g1,b1,g2,b2,g3,b3,g4,b4
        feature = (const float*)d_in[0];
        xyz     = (const float*)d_in[1];
        nidx    = d_in[2];
        W1 = (const float*)d_in[3];  W2 = (const float*)d_in[4];
        W3 = (const float*)d_in[5];  W4 = (const float*)d_in[6];
        g1 = (const float*)d_in[7];  b1 = (const float*)d_in[8];
        g2 = (const float*)d_in[9];  b2 = (const float*)d_in[10];
        g3 = (const float*)d_in[11]; b3 = (const float*)d_in[12];
        g4 = (const float*)d_in[13]; b4 = (const float*)d_in[14];
    } else {
        // reference signature order:
        // feature, xyz, W1,g1,b1, W2,g2,b2, W3,g3,b3, W4,g4,b4, neigh_idx
        feature = (const float*)d_in[0];
        xyz     = (const float*)d_in[1];
        W1 = (const float*)d_in[2];  g1 = (const float*)d_in[3];  b1 = (const float*)d_in[4];
        W2 = (const float*)d_in[5];  g2 = (const float*)d_in[6];  b2 = (const float*)d_in[7];
        W3 = (const float*)d_in[8];  g3 = (const float*)d_in[9];  b3 = (const float*)d_in[10];
        W4 = (const float*)d_in[11]; g4 = (const float*)d_in[12]; b4 = (const float*)d_in[13];
        nidx = d_in[14];
    }

    detect_idx_kind<<<1, 32>>>(nidx);

    int blocks = BATCH * NPTS / 8;
    conv2_kernel<<<blocks, 256>>>(feature, W2, g2, b2);
    main_kernel<<<blocks, 256>>>(xyz, nidx,
                                 W1, g1, b1, W3, g3, b3, W4, g4, b4,
                                 (float*)d_out);
}

// round 3
// speedup vs baseline: 2.0626x; 2.0626x over previous
#include <cuda_runtime.h>
#include <cstdint>

#define NPTS  40960
#define BATCH 4
#define KNN   16
#define DCH   64
#define HCH   32

// scratch: f = relu(bn(W2 @ feature))  -> [B*N][H]
__device__ float f_buf[(size_t)BATCH * NPTS * HCH];
__device__ int   g_is64;

// packed fp32x2 FMA (Blackwell): d = a*b + d elementwise on two packed floats
__device__ __forceinline__ void fma2(unsigned long long& d,
                                     unsigned long long a,
                                     unsigned long long b) {
    asm("fma.rn.f32x2 %0, %1, %2, %0;" : "+l"(d) : "l"(a), "l"(b));
}
__device__ __forceinline__ float unpack_sum(unsigned long long v) {
    float lo = __uint_as_float((unsigned)(v & 0xffffffffull));
    float hi = __uint_as_float((unsigned)(v >> 32));
    return lo + hi;
}

// ---------------------------------------------------------------------------
// int64 vs int32 detection for neigh_idx (jax x64 ambiguity)
// ---------------------------------------------------------------------------
__global__ void detect_idx_kind(const void* __restrict__ idx) {
    const long long* p = (const long long*)idx;
    int lane = threadIdx.x & 31;
    int cnt = 0;
    for (int i = lane; i < 256; i += 32) {
        long long v = p[i];
        if (v >= 0 && v < NPTS) cnt++;
    }
    #pragma unroll
    for (int o = 16; o; o >>= 1) cnt += __shfl_down_sync(0xffffffffu, cnt, o);
    if (lane == 0) g_is64 = (cnt > 128) ? 1 : 0;
}

// ---------------------------------------------------------------------------
// conv2: tile of 128 points per block; coalesced feature loads; scalar GEMM.
// f_buf[point][h] = relu(bn(W2 @ feature))
// ---------------------------------------------------------------------------
__global__ void __launch_bounds__(256, 4) conv2_kernel(
    const float* __restrict__ feature,
    const float* __restrict__ W2,
    const float* __restrict__ g2,
    const float* __restrict__ b2)
{
    __shared__ __align__(16) float Fs[DCH * 128];   // [d][n] 32KB
    __shared__ float W2t[DCH * HCH];                // [d][h] 8KB

    int tid = threadIdx.x;
    for (int i = tid; i < DCH * HCH; i += 256) {
        int d = i >> 5, h = i & 31;
        W2t[i] = W2[h * DCH + d];
    }
    int pg0 = blockIdx.x * 128;
    int b = pg0 / NPTS, n0 = pg0 % NPTS;           // 128 | NPTS -> single batch
    const float4* fv = (const float4*)(feature + ((size_t)b * DCH) * NPTS + n0);
    for (int i = tid; i < DCH * 32; i += 256) {
        int d = i >> 5, q = i & 31;
        ((float4*)Fs)[d * 32 + q] = __ldg(fv + (size_t)d * (NPTS / 4) + q);
    }
    __syncthreads();

    int tx = tid & 15, ty = tid >> 4;
    float acc[8][2];
    #pragma unroll
    for (int i = 0; i < 8; i++) { acc[i][0] = 0.f; acc[i][1] = 0.f; }

    #pragma unroll 4
    for (int d = 0; d < DCH; d++) {
        float w0 = W2t[d * HCH + tx];
        float w1 = W2t[d * HCH + tx + 16];
        #pragma unroll
        for (int i = 0; i < 8; i++) {
            float a = Fs[d * 128 + ty + 16 * i];
            acc[i][0] = fmaf(a, w0, acc[i][0]);
            acc[i][1] = fmaf(a, w1, acc[i][1]);
        }
    }

    const float RS = rsqrtf(1.00001f);
    float s0 = __ldg(g2 + tx) * RS,      bb0 = __ldg(b2 + tx);
    float s1 = __ldg(g2 + tx + 16) * RS, bb1 = __ldg(b2 + tx + 16);
    float* fb = f_buf + (size_t)pg0 * HCH;
    #pragma unroll
    for (int i = 0; i < 8; i++) {
        int n_loc = ty + 16 * i;
        fb[(size_t)n_loc * HCH + tx]      = fmaxf(fmaf(acc[i][0], s0, bb0), 0.f);
        fb[(size_t)n_loc * HCH + tx + 16] = fmaxf(fmaf(acc[i][1], s1, bb1), 0.f);
    }
}

// ---------------------------------------------------------------------------
// Main fused kernel: 8 points per block (A-tile 128 rows x 64 cols).
// Phase A: gather + conv1 -> smem A tile
// Phase B: conv3 GEMM with f32x2 packing along reduction dim
// Phase C: k-maxpool + conv4 (f32x2) -> out
// ---------------------------------------------------------------------------
__global__ void __launch_bounds__(256, 3) main_kernel(
    const float* __restrict__ xyz,
    const void*  __restrict__ nidx,
    const float* __restrict__ W1, const float* __restrict__ g1, const float* __restrict__ b1,
    const float* __restrict__ W3, const float* __restrict__ g3, const float* __restrict__ b3,
    const float* __restrict__ W4, const float* __restrict__ g4, const float* __restrict__ b4,
    float* __restrict__ out)
{
    // A region (32KB) is reused: [A tile 128x64] -> [Cs 128x32 | W4q 16x64xfloat4]
    __shared__ __align__(16) char smem_raw[128 * 64 * 4];
    __shared__ __align__(16) float4 W3q[16 * 32];   // [cc][h] 8KB
    __shared__ __align__(16) float  M2[8 * 64];     // [p][64] 2KB

    float*  A   = (float*)smem_raw;                 // [row][64]
    float*  Cs  = (float*)smem_raw;                 // [row][32]
    float4* W4q = (float4*)(smem_raw + 16384);      // [cc][64]

    int tid = threadIdx.x;
    // stage W3 -> W3q[cc][h] = W3[h][4cc..4cc+3]
    for (int i = tid; i < 512; i += 256) {
        int h = i & 31, cc = i >> 5;
        W3q[cc * 32 + h] = __ldg((const float4*)(W3 + h * 64) + cc);
    }

    int warp = tid >> 5, lane = tid & 31;
    int pg = blockIdx.x * 8 + warp;
    int b = pg / NPTS, n = pg % NPTS;

    const float RS = rsqrtf(1.00001f);
    const float* xb  = xyz + (size_t)b * NPTS * 3;
    const float* fbb = f_buf + (size_t)b * NPTS * HCH;

    // ---- Phase A: build A tile ----
    {
        float s1v = __ldg(g1 + lane) * RS, b1v = __ldg(b1 + lane);
        float w0 = __ldg(W1 + lane * 10 + 0);
        float w1 = __ldg(W1 + lane * 10 + 1), w2 = __ldg(W1 + lane * 10 + 2), w3 = __ldg(W1 + lane * 10 + 3);
        float w4 = __ldg(W1 + lane * 10 + 4), w5 = __ldg(W1 + lane * 10 + 5), w6 = __ldg(W1 + lane * 10 + 6);
        float w7 = __ldg(W1 + lane * 10 + 7), w8 = __ldg(W1 + lane * 10 + 8), w9 = __ldg(W1 + lane * 10 + 9);

        int is64 = g_is64;
        int jj = 0;
        size_t off = (size_t)(b * NPTS + n) * KNN;
        if (lane < KNN)
            jj = is64 ? (int)((const long long*)nidx)[off + lane]
                      : ((const int*)nidx)[off + lane];

        float cx = __ldg(xb + n * 3 + 0);
        float cy = __ldg(xb + n * 3 + 1);
        float cz = __ldg(xb + n * 3 + 2);

        // dot = w0*dist + (w1+w4)*c + (w7-w1)*p   (folded rel = c - p)
        float cterm = (w1 + w4) * cx + (w2 + w5) * cy + (w3 + w6) * cz;
        float qx = w7 - w1, qy = w8 - w2, qz = w9 - w3;

        float* Arow = A + warp * 16 * 64;
        #pragma unroll 4
        for (int k = 0; k < KNN; k++) {
            int j = __shfl_sync(0xffffffffu, jj, k);
            float px = __ldg(xb + j * 3 + 0);
            float py = __ldg(xb + j * 3 + 1);
            float pz = __ldg(xb + j * 3 + 2);
            float fn = fbb[(size_t)j * HCH + lane];
            float rx = cx - px, ry = cy - py, rz = cz - pz;
            float dist = sqrtf(fmaf(rz, rz, fmaf(ry, ry, rx * rx)));
            float dot = fmaf(w0, dist, cterm);
            dot = fmaf(qx, px, dot);
            dot = fmaf(qy, py, dot);
            dot = fmaf(qz, pz, dot);
            float fx = fmaxf(fmaf(dot, s1v, b1v), 0.f);
            Arow[k * 64 + lane]      = fn;
            Arow[k * 64 + 32 + lane] = fx;
        }
    }
    __syncthreads();

    // ---- Phase B: conv3 GEMM. thread (ty,tx): rows ty+16i, cols {tx, tx+16} ----
    int tx = tid & 15, ty = tid >> 4;
    unsigned long long acc[8][2];
    #pragma unroll
    for (int i = 0; i < 8; i++) { acc[i][0] = 0ull; acc[i][1] = 0ull; }

    const ulonglong2* A_u  = (const ulonglong2*)A;     // row = 16 entries
    const ulonglong2* W3_u = (const ulonglong2*)W3q;

    #pragma unroll 4
    for (int cc = 0; cc < 16; cc++) {
        ulonglong2 wv0 = W3_u[cc * 32 + tx];
        ulonglong2 wv1 = W3_u[cc * 32 + tx + 16];
        #pragma unroll
        for (int i = 0; i < 8; i++) {
            ulonglong2 av = A_u[(ty + 16 * i) * 16 + cc];
            fma2(acc[i][0], av.x, wv0.x);
            fma2(acc[i][0], av.y, wv0.y);
            fma2(acc[i][1], av.x, wv1.x);
            fma2(acc[i][1], av.y, wv1.y);
        }
    }

    float s3a = __ldg(g3 + tx) * RS,      b3a = __ldg(b3 + tx);
    float s3b = __ldg(g3 + tx + 16) * RS, b3b = __ldg(b3 + tx + 16);
    __syncthreads();   // all done reading A before overwriting as Cs/W4q

    #pragma unroll
    for (int i = 0; i < 8; i++) {
        int r = ty + 16 * i;
        Cs[r * 32 + tx]      = fmaxf(fmaf(unpack_sum(acc[i][0]), s3a, b3a), 0.f);
        Cs[r * 32 + tx + 16] = fmaxf(fmaf(unpack_sum(acc[i][1]), s3b, b3b), 0.f);
    }
    // stage W4 -> W4q[cc][d] = W4[d][4cc..4cc+3]  (second 16KB half)
    for (int i = tid; i < 1024; i += 256) {
        int d = i & 63, cc = i >> 6;
        W4q[cc * 64 + d] = __ldg((const float4*)(W4 + d * 64) + cc);
    }
    __syncthreads();

    // ---- Phase C: maxpool over k + center concat ----
    {
        int p = tid >> 5, h = tid & 31;       // p in [0,8)
        float m = -1e30f;
        #pragma unroll
        for (int k = 0; k < KNN; k++)
            m = fmaxf(m, Cs[(p * 16 + k) * 32 + h]);
        int pgp = blockIdx.x * 8 + p;
        int bp = pgp / NPTS, np = pgp % NPTS;
        M2[p * 64 + h] = m;
        M2[p * 64 + 32 + h] = f_buf[((size_t)bp * NPTS + np) * HCH + h];
    }
    __syncthreads();

    // ---- conv4: per point 64 -> 64, f32x2 packed ----
    {
        int p = tid >> 5, d = tid & 31;
        const ulonglong2* M_u = (const ulonglong2*)(M2 + p * 64);
        const ulonglong2* W4_u = (const ulonglong2*)W4q;
        unsigned long long a0 = 0ull, a1 = 0ull;
        #pragma unroll 4
        for (int cc = 0; cc < 16; cc++) {
            ulonglong2 av = M_u[cc];
            ulonglong2 wa = W4_u[cc * 64 + d];
            ulonglong2 wb = W4_u[cc * 64 + d + 32];
            fma2(a0, av.x, wa.x);
            fma2(a0, av.y, wa.y);
            fma2(a1, av.x, wb.x);
            fma2(a1, av.y, wb.y);
        }
        float s4a = __ldg(g4 + d) * RS,      b4a = __ldg(b4 + d);
        float s4b = __ldg(g4 + d + 32) * RS, b4b = __ldg(b4 + d + 32);
        float o0 = fmaxf(fmaf(unpack_sum(a0), s4a, b4a), 0.f);
        float o1 = fmaxf(fmaf(unpack_sum(a1), s4b, b4b), 0.f);
        int pgp = blockIdx.x * 8 + p;
        int bp = pgp / NPTS, np = pgp % NPTS;
        out[((size_t)bp * DCH + d)      * NPTS + np] = o0;
        out[((size_t)bp * DCH + d + 32) * NPTS + np] = o1;
    }
}

// ---------------------------------------------------------------------------
extern "C" void kernel_launch(void* const* d_in, const int* in_sizes, int n_in,
                              void* d_out, int out_size)
{
    const float *feature, *xyz, *W1, *W2, *W3, *W4;
    const float *g1, *b1, *g2, *b2, *g3, *b3, *g4, *b4;
    const void* nidx;

    if (in_sizes[2] == BATCH * NPTS * KNN) {
        feature = (const float*)d_in[0];
        xyz     = (const float*)d_in[1];
        nidx    = d_in[2];
        W1 = (const float*)d_in[3];  W2 = (const float*)d_in[4];
        W3 = (const float*)d_in[5];  W4 = (const float*)d_in[6];
        g1 = (const float*)d_in[7];  b1 = (const float*)d_in[8];
        g2 = (const float*)d_in[9];  b2 = (const float*)d_in[10];
        g3 = (const float*)d_in[11]; b3 = (const float*)d_in[12];
        g4 = (const float*)d_in[13]; b4 = (const float*)d_in[14];
    } else {
        feature = (const float*)d_in[0];
        xyz     = (const float*)d_in[1];
        W1 = (const float*)d_in[2];  g1 = (const float*)d_in[3];  b1 = (const float*)d_in[4];
        W2 = (const float*)d_in[5];  g2 = (const float*)d_in[6];  b2 = (const float*)d_in[7];
        W3 = (const float*)d_in[8];  g3 = (const float*)d_in[9];  b3 = (const float*)d_in[10];
        W4 = (const float*)d_in[11]; g4 = (const float*)d_in[12]; b4 = (const float*)d_in[13];
        nidx = d_in[14];
    }

    detect_idx_kind<<<1, 32>>>(nidx);
    conv2_kernel<<<BATCH * NPTS / 128, 256>>>(feature, W2, g2, b2);
    main_kernel<<<BATCH * NPTS / 8, 256>>>(xyz, nidx,
                                           W1, g1, b1, W3, g3, b3, W4, g4, b4,
                                           (float*)d_out);
}

// round 6
// speedup vs baseline: 2.2206x; 1.0766x over previous
#include <cuda_runtime.h>
#include <cstdint>

#define NPTS  40960
#define BATCH 4
#define KNN   16
#define DCH   64
#define HCH   32

// scratch: f = relu(bn(W2 @ feature))  -> [B*N][H]
__device__ float f_buf[(size_t)BATCH * NPTS * HCH];
__device__ int   g_is64;

// packed fp32x2 FMA (Blackwell): d = a*b + d elementwise on two packed floats
__device__ __forceinline__ void fma2(unsigned long long& d,
                                     unsigned long long a,
                                     unsigned long long b) {
    asm("fma.rn.f32x2 %0, %1, %2, %0;" : "+l"(d) : "l"(a), "l"(b));
}
__device__ __forceinline__ float unpack_sum(unsigned long long v) {
    float lo = __uint_as_float((unsigned)(v & 0xffffffffull));
    float hi = __uint_as_float((unsigned)(v >> 32));
    return lo + hi;
}

// ---------------------------------------------------------------------------
// conv2: tile of 128 points per block; coalesced feature loads; scalar GEMM.
// Block 0 / warp 0 additionally detects int64-vs-int32 neigh_idx encoding.
// ---------------------------------------------------------------------------
__global__ void __launch_bounds__(256, 4) conv2_kernel(
    const float* __restrict__ feature,
    const float* __restrict__ W2,
    const float* __restrict__ g2,
    const float* __restrict__ b2,
    const void*  __restrict__ nidx)
{
    __shared__ __align__(16) float Fs[DCH * 128];   // [d][n] 32KB
    __shared__ float W2t[DCH * HCH];                // [d][h] 8KB

    int tid = threadIdx.x;

    // idx-kind detection (tiny; warp 0 of block 0 only)
    if (blockIdx.x == 0 && tid < 32) {
        const long long* p = (const long long*)nidx;
        int cnt = 0;
        #pragma unroll
        for (int i = 0; i < 8; i++) {
            long long v = p[tid + 32 * i];
            if (v >= 0 && v < NPTS) cnt++;
        }
        #pragma unroll
        for (int o = 16; o; o >>= 1) cnt += __shfl_down_sync(0xffffffffu, cnt, o);
        if (tid == 0) g_is64 = (cnt > 128) ? 1 : 0;
    }

    for (int i = tid; i < DCH * HCH; i += 256) {
        int d = i >> 5, h = i & 31;
        W2t[i] = W2[h * DCH + d];
    }
    int pg0 = blockIdx.x * 128;
    int b = pg0 / NPTS, n0 = pg0 % NPTS;            // 128 | NPTS -> single batch
    const float4* fv = (const float4*)(feature + ((size_t)b * DCH) * NPTS + n0);
    for (int i = tid; i < DCH * 32; i += 256) {
        int d = i >> 5, q = i & 31;
        ((float4*)Fs)[d * 32 + q] = __ldg(fv + (size_t)d * (NPTS / 4) + q);
    }
    __syncthreads();

    int tx = tid & 15, ty = tid >> 4;
    float acc[8][2];
    #pragma unroll
    for (int i = 0; i < 8; i++) { acc[i][0] = 0.f; acc[i][1] = 0.f; }

    #pragma unroll 4
    for (int d = 0; d < DCH; d++) {
        float w0 = W2t[d * HCH + tx];
        float w1 = W2t[d * HCH + tx + 16];
        #pragma unroll
        for (int i = 0; i < 8; i++) {
            float a = Fs[d * 128 + ty + 16 * i];
            acc[i][0] = fmaf(a, w0, acc[i][0]);
            acc[i][1] = fmaf(a, w1, acc[i][1]);
        }
    }

    const float RS = rsqrtf(1.00001f);
    float s0 = __ldg(g2 + tx) * RS,      bb0 = __ldg(b2 + tx);
    float s1 = __ldg(g2 + tx + 16) * RS, bb1 = __ldg(b2 + tx + 16);
    float* fb = f_buf + (size_t)pg0 * HCH;
    #pragma unroll
    for (int i = 0; i < 8; i++) {
        int n_loc = ty + 16 * i;
        fb[(size_t)n_loc * HCH + tx]      = fmaxf(fmaf(acc[i][0], s0, bb0), 0.f);
        fb[(size_t)n_loc * HCH + tx + 16] = fmaxf(fmaf(acc[i][1], s1, bb1), 0.f);
    }
}

// ---------------------------------------------------------------------------
// Main fused kernel: 8 points per block (A-tile 128 rows x 64 cols).
// Phase A: bulk xyz loads + shfl distribution, 16-deep gather prefetch,
//          conv1 -> smem A tile
// Phase B: conv3 GEMM with f32x2 packing along reduction dim
// Phase C: k-maxpool + conv4 (f32x2) -> out
// ---------------------------------------------------------------------------
__global__ void __launch_bounds__(256, 3) main_kernel(
    const float* __restrict__ xyz,
    const void*  __restrict__ nidx,
    const float* __restrict__ W1, const float* __restrict__ g1, const float* __restrict__ b1,
    const float* __restrict__ W3, const float* __restrict__ g3, const float* __restrict__ b3,
    const float* __restrict__ W4, const float* __restrict__ g4, const float* __restrict__ b4,
    float* __restrict__ out)
{
    // A region (32KB) is reused: [A tile 128x64] -> [Cs 128x32 | W4q 16x64xfloat4]
    __shared__ __align__(16) char smem_raw[128 * 64 * 4];
    __shared__ __align__(16) float4 W3q[16 * 32];   // [cc][h] 8KB
    __shared__ __align__(16) float  M2[8 * 64];     // [p][64] 2KB

    float*  A   = (float*)smem_raw;                 // [row][64]
    float*  Cs  = (float*)smem_raw;                 // [row][32]
    float4* W4q = (float4*)(smem_raw + 16384);      // [cc][64]

    int tid = threadIdx.x;
    // stage W3 -> W3q[cc][h] = W3[h][4cc..4cc+3]
    for (int i = tid; i < 512; i += 256) {
        int h = i & 31, cc = i >> 5;
        W3q[cc * 32 + h] = __ldg((const float4*)(W3 + h * 64) + cc);
    }

    int warp = tid >> 5, lane = tid & 31;
    int pg = blockIdx.x * 8 + warp;
    int b = pg / NPTS, n = pg % NPTS;

    const float RS = rsqrtf(1.00001f);
    const float* xb  = xyz + (size_t)b * NPTS * 3;
    const float* fbb = f_buf + (size_t)b * NPTS * HCH;

    // ---- Phase A: build A tile ----
    {
        // lanes 0..15 own neighbor k = lane: load its index + xyz
        int jv = 0;
        if (lane < KNN) {
            size_t off = (size_t)(b * NPTS + n) * KNN;
            jv = g_is64 ? (int)((const long long*)nidx)[off + lane]
                        : ((const int*)nidx)[off + lane];
        }
        float nxv = 0.f, nyv = 0.f, nzv = 0.f;
        if (lane < KNN) {
            nxv = __ldg(xb + jv * 3 + 0);
            nyv = __ldg(xb + jv * 3 + 1);
            nzv = __ldg(xb + jv * 3 + 2);
        }

        // prefetch all 16 gather rows (MLP = 16)
        float fnr[KNN];
        #pragma unroll
        for (int k = 0; k < KNN; k++) {
            int j = __shfl_sync(0xffffffffu, jv, k);
            fnr[k] = fbb[(size_t)j * HCH + lane];
        }

        float s1v = __ldg(g1 + lane) * RS, b1v = __ldg(b1 + lane);
        float w0 = __ldg(W1 + lane * 10 + 0);
        float w1 = __ldg(W1 + lane * 10 + 1), w2 = __ldg(W1 + lane * 10 + 2), w3 = __ldg(W1 + lane * 10 + 3);
        float w4 = __ldg(W1 + lane * 10 + 4), w5 = __ldg(W1 + lane * 10 + 5), w6 = __ldg(W1 + lane * 10 + 6);
        float w7 = __ldg(W1 + lane * 10 + 7), w8 = __ldg(W1 + lane * 10 + 8), w9 = __ldg(W1 + lane * 10 + 9);

        float cx = __ldg(xb + n * 3 + 0);
        float cy = __ldg(xb + n * 3 + 1);
        float cz = __ldg(xb + n * 3 + 2);

        // dot = w0*dist + cterm + (w7-w1,...)·p   (rel = c - p folded)
        float cterm = (w1 + w4) * cx + (w2 + w5) * cy + (w3 + w6) * cz;
        float qx = w7 - w1, qy = w8 - w2, qz = w9 - w3;

        float* Arow = A + warp * 16 * 64;
        #pragma unroll
        for (int k = 0; k < KNN; k++) {
            float px = __shfl_sync(0xffffffffu, nxv, k);
            float py = __shfl_sync(0xffffffffu, nyv, k);
            float pz = __shfl_sync(0xffffffffu, nzv, k);
            float rx = cx - px, ry = cy - py, rz = cz - pz;
            float dist = sqrtf(fmaf(rz, rz, fmaf(ry, ry, rx * rx)));
            float dot = fmaf(w0, dist, cterm);
            dot = fmaf(qx, px, dot);
            dot = fmaf(qy, py, dot);
            dot = fmaf(qz, pz, dot);
            float fx = fmaxf(fmaf(dot, s1v, b1v), 0.f);
            Arow[k * 64 + lane]      = fnr[k];
            Arow[k * 64 + 32 + lane] = fx;
        }
    }
    __syncthreads();

    // ---- Phase B: conv3 GEMM. thread (ty,tx): rows ty+16i, cols {tx, tx+16} ----
    int tx = tid & 15, ty = tid >> 4;
    unsigned long long acc[8][2];
    #pragma unroll
    for (int i = 0; i < 8; i++) { acc[i][0] = 0ull; acc[i][1] = 0ull; }

    const ulonglong2* A_u  = (const ulonglong2*)A;     // row = 16 entries
    const ulonglong2* W3_u = (const ulonglong2*)W3q;

    #pragma unroll 4
    for (int cc = 0; cc < 16; cc++) {
        ulonglong2 wv0 = W3_u[cc * 32 + tx];
        ulonglong2 wv1 = W3_u[cc * 32 + tx + 16];
        #pragma unroll
        for (int i = 0; i < 8; i++) {
            ulonglong2 av = A_u[(ty + 16 * i) * 16 + cc];
            fma2(acc[i][0], av.x, wv0.x);
            fma2(acc[i][0], av.y, wv0.y);
            fma2(acc[i][1], av.x, wv1.x);
            fma2(acc[i][1], av.y, wv1.y);
        }
    }

    float s3a = __ldg(g3 + tx) * RS,      b3a = __ldg(b3 + tx);
    float s3b = __ldg(g3 + tx + 16) * RS, b3b = __ldg(b3 + tx + 16);
    __syncthreads();   // all done reading A before overwriting as Cs/W4q

    #pragma unroll
    for (int i = 0; i < 8; i++) {
        int r = ty + 16 * i;
        Cs[r * 32 + tx]      = fmaxf(fmaf(unpack_sum(acc[i][0]), s3a, b3a), 0.f);
        Cs[r * 32 + tx + 16] = fmaxf(fmaf(unpack_sum(acc[i][1]), s3b, b3b), 0.f);
    }
    // stage W4 -> W4q[cc][d] = W4[d][4cc..4cc+3]  (second 16KB half)
    for (int i = tid; i < 1024; i += 256) {
        int d = i & 63, cc = i >> 6;
        W4q[cc * 64 + d] = __ldg((const float4*)(W4 + d * 64) + cc);
    }
    __syncthreads();

    // ---- Phase C: maxpool over k + center concat ----
    {
        int p = tid >> 5, h = tid & 31;       // p in [0,8)
        float m = -1e30f;
        #pragma unroll
        for (int k = 0; k < KNN; k++)
            m = fmaxf(m, Cs[(p * 16 + k) * 32 + h]);
        int pgp = blockIdx.x * 8 + p;
        int bp = pgp / NPTS, np = pgp % NPTS;
        M2[p * 64 + h] = m;
        M2[p * 64 + 32 + h] = f_buf[((size_t)bp * NPTS + np) * HCH + h];
    }
    __syncthreads();

    // ---- conv4: per point 64 -> 64, f32x2 packed ----
    {
        int p = tid >> 5, d = tid & 31;
        const ulonglong2* M_u = (const ulonglong2*)(M2 + p * 64);
        const ulonglong2* W4_u = (const ulonglong2*)W4q;
        unsigned long long a0 = 0ull, a1 = 0ull;
        #pragma unroll 4
        for (int cc = 0; cc < 16; cc++) {
            ulonglong2 av = M_u[cc];
            ulonglong2 wa = W4_u[cc * 64 + d];
            ulonglong2 wb = W4_u[cc * 64 + d + 32];
            fma2(a0, av.x, wa.x);
            fma2(a0, av.y, wa.y);
            fma2(a1, av.x, wb.x);
            fma2(a1, av.y, wb.y);
        }
        float s4a = __ldg(g4 + d) * RS,      b4a = __ldg(b4 + d);
        float s4b = __ldg(g4 + d + 32) * RS, b4b = __ldg(b4 + d + 32);
        float o0 = fmaxf(fmaf(unpack_sum(a0), s4a, b4a), 0.f);
        float o1 = fmaxf(fmaf(unpack_sum(a1), s4b, b4b), 0.f);
        int pgp = blockIdx.x * 8 + p;
        int bp = pgp / NPTS, np = pgp % NPTS;
        out[((size_t)bp * DCH + d)      * NPTS + np] = o0;
        out[((size_t)bp * DCH + d + 32) * NPTS + np] = o1;
    }
}

// ---------------------------------------------------------------------------
extern "C" void kernel_launch(void* const* d_in, const int* in_sizes, int n_in,
                              void* d_out, int out_size)
{
    const float *feature, *xyz, *W1, *W2, *W3, *W4;
    const float *g1, *b1, *g2, *b2, *g3, *b3, *g4, *b4;
    const void* nidx;

    if (in_sizes[2] == BATCH * NPTS * KNN) {
        feature = (const float*)d_in[0];
        xyz     = (const float*)d_in[1];
        nidx    = d_in[2];
        W1 = (const float*)d_in[3];  W2 = (const float*)d_in[4];
        W3 = (const float*)d_in[5];  W4 = (const float*)d_in[6];
        g1 = (const float*)d_in[7];  b1 = (const float*)d_in[8];
        g2 = (const float*)d_in[9];  b2 = (const float*)d_in[10];
        g3 = (const float*)d_in[11]; b3 = (const float*)d_in[12];
        g4 = (const float*)d_in[13]; b4 = (const float*)d_in[14];
    } else {
        feature = (const float*)d_in[0];
        xyz     = (const float*)d_in[1];
        W1 = (const float*)d_in[2];  g1 = (const float*)d_in[3];  b1 = (const float*)d_in[4];
        W2 = (const float*)d_in[5];  g2 = (const float*)d_in[6];  b2 = (const float*)d_in[7];
        W3 = (const float*)d_in[8];  g3 = (const float*)d_in[9];  b3 = (const float*)d_in[10];
        W4 = (const float*)d_in[11]; g4 = (const float*)d_in[12]; b4 = (const float*)d_in[13];
        nidx = d_in[14];
    }

    conv2_kernel<<<BATCH * NPTS / 128, 256>>>(feature, W2, g2, b2, nidx);
    main_kernel<<<BATCH * NPTS / 8, 256>>>(xyz, nidx,
                                           W1, g1, b1, W3, g3, b3, W4, g4, b4,
                                           (float*)d_out);
}

// round 8
// speedup vs baseline: 2.4392x; 1.0985x over previous
#include <cuda_runtime.h>
#include <cstdint>

#define NPTS  40960
#define BATCH 4
#define KNN   16
#define DCH   64
#define HCH   32

// scratch: f = relu(bn(W2 @ feature))  -> [B*N][H]
__device__ float f_buf[(size_t)BATCH * NPTS * HCH];
__device__ int   g_is64;

// packed fp32x2 FMA (Blackwell): d = a*b + d elementwise on two packed floats
__device__ __forceinline__ void fma2(unsigned long long& d,
                                     unsigned long long a,
                                     unsigned long long b) {
    asm("fma.rn.f32x2 %0, %1, %2, %0;" : "+l"(d) : "l"(a), "l"(b));
}
__device__ __forceinline__ float unpack_sum(unsigned long long v) {
    float lo = __uint_as_float((unsigned)(v & 0xffffffffull));
    float hi = __uint_as_float((unsigned)(v >> 32));
    return lo + hi;
}

// ---------------------------------------------------------------------------
// conv2: tile of 128 points per block; coalesced feature loads; scalar GEMM.
// Block 0 / warp 0 additionally detects int64-vs-int32 neigh_idx encoding.
// ---------------------------------------------------------------------------
__global__ void __launch_bounds__(256, 4) conv2_kernel(
    const float* __restrict__ feature,
    const float* __restrict__ W2,
    const float* __restrict__ g2,
    const float* __restrict__ b2,
    const void*  __restrict__ nidx)
{
    __shared__ __align__(16) float Fs[DCH * 128];   // [d][n] 32KB
    __shared__ float W2t[DCH * HCH];                // [d][h] 8KB

    int tid = threadIdx.x;

    if (blockIdx.x == 0 && tid < 32) {
        const long long* p = (const long long*)nidx;
        int cnt = 0;
        #pragma unroll
        for (int i = 0; i < 8; i++) {
            long long v = p[tid + 32 * i];
            if (v >= 0 && v < NPTS) cnt++;
        }
        #pragma unroll
        for (int o = 16; o; o >>= 1) cnt += __shfl_down_sync(0xffffffffu, cnt, o);
        if (tid == 0) g_is64 = (cnt > 128) ? 1 : 0;
    }

    for (int i = tid; i < DCH * HCH; i += 256) {
        int d = i >> 5, h = i & 31;
        W2t[i] = W2[h * DCH + d];
    }
    int pg0 = blockIdx.x * 128;
    int b = pg0 / NPTS, n0 = pg0 % NPTS;
    const float4* fv = (const float4*)(feature + ((size_t)b * DCH) * NPTS + n0);
    for (int i = tid; i < DCH * 32; i += 256) {
        int d = i >> 5, q = i & 31;
        ((float4*)Fs)[d * 32 + q] = __ldg(fv + (size_t)d * (NPTS / 4) + q);
    }
    __syncthreads();

    int tx = tid & 15, ty = tid >> 4;
    float acc[8][2];
    #pragma unroll
    for (int i = 0; i < 8; i++) { acc[i][0] = 0.f; acc[i][1] = 0.f; }

    #pragma unroll 4
    for (int d = 0; d < DCH; d++) {
        float w0 = W2t[d * HCH + tx];
        float w1 = W2t[d * HCH + tx + 16];
        #pragma unroll
        for (int i = 0; i < 8; i++) {
            float a = Fs[d * 128 + ty + 16 * i];
            acc[i][0] = fmaf(a, w0, acc[i][0]);
            acc[i][1] = fmaf(a, w1, acc[i][1]);
        }
    }

    const float RS = rsqrtf(1.00001f);
    float s0 = __ldg(g2 + tx) * RS,      bb0 = __ldg(b2 + tx);
    float s1 = __ldg(g2 + tx + 16) * RS, bb1 = __ldg(b2 + tx + 16);
    float* fb = f_buf + (size_t)pg0 * HCH;
    #pragma unroll
    for (int i = 0; i < 8; i++) {
        int n_loc = ty + 16 * i;
        fb[(size_t)n_loc * HCH + tx]      = fmaxf(fmaf(acc[i][0], s0, bb0), 0.f);
        fb[(size_t)n_loc * HCH + tx + 16] = fmaxf(fmaf(acc[i][1], s1, bb1), 0.f);
    }
}

// ---------------------------------------------------------------------------
// Main fused kernel: 8 points per block.
// Phase A: gather + conv1 -> smem A[128x64]
// Phase B: conv3 GEMM (f32x2 packed along reduction dim)
// Phase C: k-maxpool; conv4 by 2 warps (broadcast-M, contiguous W4 rows);
//          smem-staged coalesced output.
// ---------------------------------------------------------------------------
__global__ void __launch_bounds__(256, 3) main_kernel(
    const float* __restrict__ xyz,
    const void*  __restrict__ nidx,
    const float* __restrict__ W1, const float* __restrict__ g1, const float* __restrict__ b1,
    const float* __restrict__ W3, const float* __restrict__ g3, const float* __restrict__ b3,
    const float* __restrict__ W4, const float* __restrict__ g4, const float* __restrict__ b4,
    float* __restrict__ out)
{
    // 32KB region reused: [A 128x64] -> [Cs 128x32 | W4t 64x64 (c-major)]
    __shared__ __align__(16) char smem_raw[128 * 64 * 4];
    __shared__ __align__(16) float4 W3q[16 * 32];   // [cc][h] 8KB
    __shared__ __align__(16) float  M2[8 * 64];     // [p][64] 2KB
    __shared__ __align__(16) float  Os[64 * 10];    // padded out stage 2.5KB

    float*  A   = (float*)smem_raw;                 // [row][64]
    float*  Cs  = (float*)smem_raw;                 // [row][32]
    float*  W4t = (float*)(smem_raw + 16384);       // [c][d] 16KB

    int tid = threadIdx.x;
    for (int i = tid; i < 512; i += 256) {
        int h = i & 31, cc = i >> 5;
        W3q[cc * 32 + h] = __ldg((const float4*)(W3 + h * 64) + cc);
    }

    int warp = tid >> 5, lane = tid & 31;
    int pg = blockIdx.x * 8 + warp;
    int b = pg / NPTS, n = pg % NPTS;
    int n0 = (blockIdx.x * 8) % NPTS;
    int b0 = (blockIdx.x * 8) / NPTS;

    const float RS = rsqrtf(1.00001f);
    const float* xb  = xyz + (size_t)b * NPTS * 3;
    const float* fbb = f_buf + (size_t)b * NPTS * HCH;

    // ---- Phase A ----
    {
        int jv = 0;
        if (lane < KNN) {
            size_t off = (size_t)(b * NPTS + n) * KNN;
            jv = g_is64 ? (int)((const long long*)nidx)[off + lane]
                        : ((const int*)nidx)[off + lane];
        }
        float nxv = 0.f, nyv = 0.f, nzv = 0.f;
        if (lane < KNN) {
            nxv = __ldg(xb + jv * 3 + 0);
            nyv = __ldg(xb + jv * 3 + 1);
            nzv = __ldg(xb + jv * 3 + 2);
        }

        float fnr[KNN];
        #pragma unroll
        for (int k = 0; k < KNN; k++) {
            int j = __shfl_sync(0xffffffffu, jv, k);
            fnr[k] = fbb[(size_t)j * HCH + lane];
        }

        float s1v = __ldg(g1 + lane) * RS, b1v = __ldg(b1 + lane);
        float w0 = __ldg(W1 + lane * 10 + 0);
        float w1 = __ldg(W1 + lane * 10 + 1), w2 = __ldg(W1 + lane * 10 + 2), w3 = __ldg(W1 + lane * 10 + 3);
        float w4 = __ldg(W1 + lane * 10 + 4), w5 = __ldg(W1 + lane * 10 + 5), w6 = __ldg(W1 + lane * 10 + 6);
        float w7 = __ldg(W1 + lane * 10 + 7), w8 = __ldg(W1 + lane * 10 + 8), w9 = __ldg(W1 + lane * 10 + 9);

        float cx = __ldg(xb + n * 3 + 0);
        float cy = __ldg(xb + n * 3 + 1);
        float cz = __ldg(xb + n * 3 + 2);

        float cterm = (w1 + w4) * cx + (w2 + w5) * cy + (w3 + w6) * cz;
        float qx = w7 - w1, qy = w8 - w2, qz = w9 - w3;

        float* Arow = A + warp * 16 * 64;
        #pragma unroll
        for (int k = 0; k < KNN; k++) {
            float px = __shfl_sync(0xffffffffu, nxv, k);
            float py = __shfl_sync(0xffffffffu, nyv, k);
            float pz = __shfl_sync(0xffffffffu, nzv, k);
            float rx = cx - px, ry = cy - py, rz = cz - pz;
            float dist = sqrtf(fmaf(rz, rz, fmaf(ry, ry, rx * rx)));
            float dot = fmaf(w0, dist, cterm);
            dot = fmaf(qx, px, dot);
            dot = fmaf(qy, py, dot);
            dot = fmaf(qz, pz, dot);
            float fx = fmaxf(fmaf(dot, s1v, b1v), 0.f);
            Arow[k * 64 + lane]      = fnr[k];
            Arow[k * 64 + 32 + lane] = fx;
        }
    }
    __syncthreads();

    // ---- Phase B: conv3 GEMM ----
    int tx = tid & 15, ty = tid >> 4;
    unsigned long long acc[8][2];
    #pragma unroll
    for (int i = 0; i < 8; i++) { acc[i][0] = 0ull; acc[i][1] = 0ull; }

    const ulonglong2* A_u  = (const ulonglong2*)A;
    const ulonglong2* W3_u = (const ulonglong2*)W3q;

    #pragma unroll 4
    for (int cc = 0; cc < 16; cc++) {
        ulonglong2 wv0 = W3_u[cc * 32 + tx];
        ulonglong2 wv1 = W3_u[cc * 32 + tx + 16];
        #pragma unroll
        for (int i = 0; i < 8; i++) {
            ulonglong2 av = A_u[(ty + 16 * i) * 16 + cc];
            fma2(acc[i][0], av.x, wv0.x);
            fma2(acc[i][0], av.y, wv0.y);
            fma2(acc[i][1], av.x, wv1.x);
            fma2(acc[i][1], av.y, wv1.y);
        }
    }

    float s3a = __ldg(g3 + tx) * RS,      b3a = __ldg(b3 + tx);
    float s3b = __ldg(g3 + tx + 16) * RS, b3b = __ldg(b3 + tx + 16);
    __syncthreads();   // done reading A

    #pragma unroll
    for (int i = 0; i < 8; i++) {
        int r = ty + 16 * i;
        Cs[r * 32 + tx]      = fmaxf(fmaf(unpack_sum(acc[i][0]), s3a, b3a), 0.f);
        Cs[r * 32 + tx + 16] = fmaxf(fmaf(unpack_sum(acc[i][1]), s3b, b3b), 0.f);
    }
    // stage W4 transposed: W4t[c][d] = W4[d][c]  (contiguous-d rows)
    for (int i = tid; i < 1024; i += 256) {
        int d = i & 63, c4 = i >> 6;               // c4 in [0,16)
        float4 wv = __ldg((const float4*)(W4 + d * 64) + c4);
        W4t[(4 * c4 + 0) * 64 + d] = wv.x;
        W4t[(4 * c4 + 1) * 64 + d] = wv.y;
        W4t[(4 * c4 + 2) * 64 + d] = wv.z;
        W4t[(4 * c4 + 3) * 64 + d] = wv.w;
    }
    __syncthreads();

    // ---- Phase C: maxpool over k + center concat ----
    {
        float m = -1e30f;
        #pragma unroll
        for (int k = 0; k < KNN; k++)
            m = fmaxf(m, Cs[(warp * 16 + k) * 32 + lane]);
        M2[warp * 64 + lane]      = m;
        M2[warp * 64 + 32 + lane] = fbb[(size_t)n * HCH + lane];
    }
    __syncthreads();

    // ---- conv4 by warps 0,1: lane+32*warp = output channel, loop 8 points ----
    if (warp < 2) {
        int d = lane + 32 * warp;
        float a4[8];
        #pragma unroll
        for (int pp = 0; pp < 8; pp++) a4[pp] = 0.f;
        const float4* M2v = (const float4*)M2;   // [p][16]
        #pragma unroll 4
        for (int cc = 0; cc < 16; cc++) {
            float w0 = W4t[(4 * cc + 0) * 64 + d];
            float w1 = W4t[(4 * cc + 1) * 64 + d];
            float w2 = W4t[(4 * cc + 2) * 64 + d];
            float w3 = W4t[(4 * cc + 3) * 64 + d];
            #pragma unroll
            for (int pp = 0; pp < 8; pp++) {
                float4 mv = M2v[pp * 16 + cc];
                a4[pp] = fmaf(w0, mv.x, a4[pp]);
                a4[pp] = fmaf(w1, mv.y, a4[pp]);
                a4[pp] = fmaf(w2, mv.z, a4[pp]);
                a4[pp] = fmaf(w3, mv.w, a4[pp]);
            }
        }
        float s4 = __ldg(g4 + d) * RS, b4v = __ldg(b4 + d);
        #pragma unroll
        for (int pp = 0; pp < 8; pp++)
            Os[d * 10 + pp] = fmaxf(fmaf(a4[pp], s4, b4v), 0.f);
    }
    __syncthreads();

    // ---- coalesced output: 8 block-points are contiguous in n ----
    {
        int d = tid >> 2, pq = tid & 3;            // d in [0,64), pq in [0,4)
        float2 v;
        v.x = Os[d * 10 + 2 * pq];
        v.y = Os[d * 10 + 2 * pq + 1];
        *(float2*)(out + ((size_t)b0 * DCH + d) * NPTS + n0 + 2 * pq) = v;
    }
}

// ---------------------------------------------------------------------------
extern "C" void kernel_launch(void* const* d_in, const int* in_sizes, int n_in,
                              void* d_out, int out_size)
{
    const float *feature, *xyz, *W1, *W2, *W3, *W4;
    const float *g1, *b1, *g2, *b2, *g3, *b3, *g4, *b4;
    const void* nidx;

    if (in_sizes[2] == BATCH * NPTS * KNN) {
        feature = (const float*)d_in[0];
        xyz     = (const float*)d_in[1];
        nidx    = d_in[2];
        W1 = (const float*)d_in[3];  W2 = (const float*)d_in[4];
        W3 = (const float*)d_in[5];  W4 = (const float*)d_in[6];
        g1 = (const float*)d_in[7];  b1 = (const float*)d_in[8];
        g2 = (const float*)d_in[9];  b2 = (const float*)d_in[10];
        g3 = (const float*)d_in[11]; b3 = (const float*)d_in[12];
        g4 = (const float*)d_in[13]; b4 = (const float*)d_in[14];
    } else {
        feature = (const float*)d_in[0];
        xyz     = (const float*)d_in[1];
        W1 = (const float*)d_in[2];  g1 = (const float*)d_in[3];  b1 = (const float*)d_in[4];
        W2 = (const float*)d_in[5];  g2 = (const float*)d_in[6];  b2 = (const float*)d_in[7];
        W3 = (const float*)d_in[8];  g3 = (const float*)d_in[9];  b3 = (const float*)d_in[10];
        W4 = (const float*)d_in[11]; g4 = (const float*)d_in[12]; b4 = (const float*)d_in[13];
        nidx = d_in[14];
    }

    conv2_kernel<<<BATCH * NPTS / 128, 256>>>(feature, W2, g2, b2, nidx);
    main_kernel<<<BATCH * NPTS / 8, 256>>>(xyz, nidx,
                                           W1, g1, b1, W3, g3, b3, W4, g4, b4,
                                           (float*)d_out);
}